// round 16
// baseline (speedup 1.0000x reference)
#include <cuda_runtime.h>
#include <cuda_fp16.h>
#include <cstdint>
#include <cmath>

// Problem constants
#define B_  4
#define T_  2048
#define C_  1024
#define H_  2048
#define M_  (B_*T_)
#define SCALE_ 0.03125f             // 1024^-0.5
#define SCALE_LOG2E 0.045084439f    // SCALE_ * log2(e)

// Tiling: CTA 128x128, K-stage 32 halves, 4-stage cp.async pipeline
// 4 warps as 2(M) x 2(N); warp tile 64x64
#define BKH 32
#define GTHREADS 128                   // GEMM kernels
#define PITCH 80                       // bytes per 32-half row (16B-aligned, conflict-free)
#define STG   20480                    // bytes per stage: A 128*80 + B 128*80
#define SOFF_B 10240
#define NSTAGE 4
#define SINV_OFF 81920                 // per-row 1/sum cache (pv)
#define SMEM_BYTES 82432               // 4 stages + sinv[128]
#define TSTR 136                       // V^T transpose pitch (halves)

// prep grid split
#define XBLKS 4096                     // x convert: 4096 blocks * 2048 elems = M_*C_
#define WBLKS (3*2048)                 // W transpose: 3 matrices * (32x64) 32x32-tiles

// Scratch (static device globals)
__device__ __align__(256) __half g_xh  [(size_t)M_ * C_];
__device__ __align__(256) __half g_wth [(size_t)3  * H_ * C_];  // W^T [z][H][C]
__device__ __align__(256) __half g_qh  [(size_t)M_ * H_];
__device__ __align__(256) __half g_kh  [(size_t)M_ * H_];
__device__ __align__(256) __half g_vth [(size_t)B_ * H_ * T_];  // V^T [b][H][T]
__device__ __align__(256) __half g_p   [(size_t)B_ * T_ * T_];  // unnormalized exp fp16
__device__ __align__(256) float  g_part[(size_t)M_ * 32];       // per-(row,tile,half) sums

// ---------------------------------------------------------------------------
__device__ __forceinline__ uint32_t smem_u32(const void* p) {
    uint32_t a;
    asm("{ .reg .u64 t; cvta.to.shared.u64 t, %1; cvt.u32.u64 %0, t; }"
        : "=r"(a) : "l"(p));
    return a;
}
__device__ __forceinline__ void cpasync16(uint32_t dst, const void* src) {
    asm volatile("cp.async.cg.shared.global [%0], [%1], 16;"
                 :: "r"(dst), "l"(src) : "memory");
}
__device__ __forceinline__ void ldm4(uint32_t* r, uint32_t a) {
    asm volatile("ldmatrix.sync.aligned.m8n8.x4.shared.b16 {%0,%1,%2,%3}, [%4];"
        : "=r"(r[0]), "=r"(r[1]), "=r"(r[2]), "=r"(r[3]) : "r"(a));
}
__device__ __forceinline__ void mma16816(float* c, const uint32_t* a, const uint32_t* b) {
    asm volatile(
        "mma.sync.aligned.m16n8k16.row.col.f32.f16.f16.f32 "
        "{%0,%1,%2,%3}, {%4,%5,%6,%7}, {%8,%9}, {%0,%1,%2,%3};"
        : "+f"(c[0]), "+f"(c[1]), "+f"(c[2]), "+f"(c[3])
        : "r"(a[0]), "r"(a[1]), "r"(a[2]), "r"(a[3]), "r"(b[0]), "r"(b[1]));
}

// ---------------------------------------------------------------------------
// NT fp16 GEMM: acc = A[row0:+128, k] . B[col0:+128, k]^T over ktiles*32 k's.
// 4 warps, warp tile 64x64, 4-stage cp.async pipeline, fragment prefetch.
// OUT=0: qk-exp epilogue -> fp16 exp2(acc*scale) to Cptr, row partials to rscale[]
// OUT=1: fp16 out + bias (q/k projection)
// OUT=2: fp16 out + bias, transposed through smem (V^T)
// OUT=3: fp32 out * per-row 1/sum (pv); rscale = g_part slice, reduced in prologue
// Requires ktiles >= 3.
// ---------------------------------------------------------------------------
template<int OUT>
__device__ void gemm_h(const __half* __restrict__ A, int lda,
                       const __half* __restrict__ Bm, int ldb,
                       void* __restrict__ Cptr, int ldc,
                       int row0, int col0, int ktiles,
                       const float* __restrict__ bias, float scale,
                       float* __restrict__ rscale)
{
    extern __shared__ char dsm[];
    const uint32_t sb = smem_u32(dsm);
    const int tid  = threadIdx.x;
    const int lane = tid & 31;
    const int warp = tid >> 5;
    const int wm   = warp & 1;        // M half (64 rows)
    const int wn   = warp >> 1;       // N half (64 cols)
    const int g    = lane >> 2;
    const int c    = lane & 3;

    // pv prologue: reduce 32 partial sums per row -> sinv (visible after first sync)
    float* sinv = (float*)(dsm + SINV_OFF);
    if (OUT == 3) {
        const float4* pp = (const float4*)(rscale + (size_t)(row0 + tid) * 32);
        float4 v0 = pp[0], v1 = pp[1], v2 = pp[2], v3 = pp[3];
        float4 v4 = pp[4], v5 = pp[5], v6 = pp[6], v7 = pp[7];
        float s = v0.x+v0.y+v0.z+v0.w + v1.x+v1.y+v1.z+v1.w
                + v2.x+v2.y+v2.z+v2.w + v3.x+v3.y+v3.z+v3.w
                + v4.x+v4.y+v4.z+v4.w + v5.x+v5.y+v5.z+v5.w
                + v6.x+v6.y+v6.z+v6.w + v7.x+v7.y+v7.z+v7.w;
        sinv[tid] = 1.0f / s;
    }

    float acc[4][8][4];
    #pragma unroll
    for (int i = 0; i < 4; i++)
        #pragma unroll
        for (int j = 0; j < 8; j++)
            #pragma unroll
            for (int l = 0; l < 4; l++) acc[i][j][l] = 0.0f;

    auto stage = [&](int kt) {
        const uint32_t ss = sb + (kt & (NSTAGE - 1)) * STG;
        const int k0 = kt * BKH;
        #pragma unroll
        for (int i = 0; i < 4; i++) {            // A: 128 rows x 4 chunks
            const int idx = i * GTHREADS + tid;
            const int r = idx >> 2, ch = idx & 3;
            cpasync16(ss + r * PITCH + ch * 16,
                      A + (size_t)(row0 + r) * lda + k0 + ch * 8);
        }
        #pragma unroll
        for (int i = 0; i < 4; i++) {            // B: 128 rows x 4 chunks
            const int idx = i * GTHREADS + tid;
            const int r = idx >> 2, ch = idx & 3;
            cpasync16(ss + SOFF_B + r * PITCH + ch * 16,
                      Bm + (size_t)(col0 + r) * ldb + k0 + ch * 8);
        }
        asm volatile("cp.async.commit_group;" ::: "memory");
    };

    // ldmatrix per-lane address components (within a stage)
    const uint32_t a_off = (uint32_t)((wm * 64 + (lane & 15)) * PITCH + ((lane >> 4) << 4));
    const uint32_t b_off = (uint32_t)(SOFF_B
                         + (wn * 64 + (lane & 7) + ((lane >> 4) << 3)) * PITCH
                         + (((lane >> 3) & 1) << 4));

    auto compute = [&](int kt) {
        const uint32_t ss = sb + (kt & (NSTAGE - 1)) * STG;
        const uint32_t sa = ss + a_off;
        const uint32_t sbb = ss + b_off;
        uint32_t af[2][4][4], bf[2][4][4];
        #pragma unroll
        for (int kk = 0; kk < 2; kk++) {
            #pragma unroll
            for (int mi = 0; mi < 4; mi++)
                ldm4(af[kk][mi], sa + mi * (16 * PITCH) + kk * 32);
            #pragma unroll
            for (int np = 0; np < 4; np++)
                ldm4(bf[kk][np], sbb + np * (16 * PITCH) + kk * 32);
        }
        #pragma unroll
        for (int kk = 0; kk < 2; kk++)
            #pragma unroll
            for (int mi = 0; mi < 4; mi++)
                #pragma unroll
                for (int ni = 0; ni < 8; ni++)
                    mma16816(acc[mi][ni], af[kk][mi],
                             &bf[kk][ni >> 1][(ni & 1) * 2]);
    };

    // 4-stage cp.async pipeline, ONE syncthreads per iteration
    stage(0);
    stage(1);
    stage(2);
    for (int kt = 0; kt < ktiles; kt++) {
        const int rem = ktiles - 1 - kt;
        if (rem >= 2)      asm volatile("cp.async.wait_group 2;" ::: "memory");
        else if (rem == 1) asm volatile("cp.async.wait_group 1;" ::: "memory");
        else               asm volatile("cp.async.wait_group 0;" ::: "memory");
        __syncthreads();
        if (kt + 3 < ktiles) stage(kt + 3);
        compute(kt);
    }
    __syncthreads();   // before epilogue smem reuse (OUT==2)

    // ------------------------------- epilogue -------------------------------
    if (OUT == 0) {
        // exp2(acc*scale*log2e) -> fp16 P; per-row partial sums -> rscale slots
        __half* P = (__half*)Cptr;
        const int bj = col0 >> 7;
        const bool diag = (row0 == col0);
        #pragma unroll
        for (int mi = 0; mi < 4; mi++) {
            const int r = row0 + wm * 64 + mi * 16 + g;
            float s0 = 0.0f, s1 = 0.0f;
            #pragma unroll
            for (int ni = 0; ni < 8; ni++) {
                const int col = col0 + wn * 64 + ni * 8 + 2 * c;
                float e0 = exp2f(acc[mi][ni][0] * scale);
                float e1 = exp2f(acc[mi][ni][1] * scale);
                float e2 = exp2f(acc[mi][ni][2] * scale);
                float e3 = exp2f(acc[mi][ni][3] * scale);
                if (diag) {
                    if (col     > r    ) e0 = 0.0f;
                    if (col + 1 > r    ) e1 = 0.0f;
                    if (col     > r + 8) e2 = 0.0f;
                    if (col + 1 > r + 8) e3 = 0.0f;
                }
                s0 += e0 + e1;
                s1 += e2 + e3;
                *(__half2*)(P + (size_t)r       * ldc + col) = __floats2half2_rn(e0, e1);
                *(__half2*)(P + (size_t)(r + 8) * ldc + col) = __floats2half2_rn(e2, e3);
            }
            s0 += __shfl_xor_sync(0xffffffffu, s0, 1);
            s0 += __shfl_xor_sync(0xffffffffu, s0, 2);
            s1 += __shfl_xor_sync(0xffffffffu, s1, 1);
            s1 += __shfl_xor_sync(0xffffffffu, s1, 2);
            if (c == 0) {
                rscale[(size_t)r       * 32 + bj * 2 + wn] = s0;
                rscale[(size_t)(r + 8) * 32 + bj * 2 + wn] = s1;
            }
        }
    } else if (OUT == 3) {
        float* C = (float*)Cptr;
        #pragma unroll
        for (int mi = 0; mi < 4; mi++) {
            const int ml = wm * 64 + mi * 16 + g;
            const int m  = row0 + ml;
            const float s0 = sinv[ml], s1 = sinv[ml + 8];
            #pragma unroll
            for (int ni = 0; ni < 8; ni++) {
                const int col = col0 + wn * 64 + ni * 8 + 2 * c;
                float2 o0 = make_float2(acc[mi][ni][0] * s0, acc[mi][ni][1] * s0);
                float2 o1 = make_float2(acc[mi][ni][2] * s1, acc[mi][ni][3] * s1);
                *(float2*)(C + (size_t)m       * ldc + col) = o0;
                *(float2*)(C + (size_t)(m + 8) * ldc + col) = o1;
            }
        }
    } else if (OUT == 1) {
        __half* C = (__half*)Cptr;
        #pragma unroll
        for (int mi = 0; mi < 4; mi++) {
            const int m = row0 + wm * 64 + mi * 16 + g;
            #pragma unroll
            for (int ni = 0; ni < 8; ni++) {
                const int col = col0 + wn * 64 + ni * 8 + 2 * c;
                const float b0 = bias[col], b1 = bias[col + 1];
                __half2 h0 = __floats2half2_rn(acc[mi][ni][0] + b0, acc[mi][ni][1] + b1);
                __half2 h1 = __floats2half2_rn(acc[mi][ni][2] + b0, acc[mi][ni][3] + b1);
                *(__half2*)(C + (size_t)m       * ldc + col) = h0;
                *(__half2*)(C + (size_t)(m + 8) * ldc + col) = h1;
            }
        }
    } else {
        // V^T: transpose 128(t) x 128(h) tile through smem, coalesced 16B stores
        __half* ts = (__half*)dsm;
        #pragma unroll
        for (int mi = 0; mi < 4; mi++) {
            const int ml = wm * 64 + mi * 16 + g;
            #pragma unroll
            for (int ni = 0; ni < 8; ni++) {
                const int nl = wn * 64 + ni * 8 + 2 * c;
                const float b0 = bias[col0 + nl], b1 = bias[col0 + nl + 1];
                ts[(nl    ) * TSTR + ml    ] = __float2half_rn(acc[mi][ni][0] + b0);
                ts[(nl + 1) * TSTR + ml    ] = __float2half_rn(acc[mi][ni][1] + b1);
                ts[(nl    ) * TSTR + ml + 8] = __float2half_rn(acc[mi][ni][2] + b0);
                ts[(nl + 1) * TSTR + ml + 8] = __float2half_rn(acc[mi][ni][3] + b1);
            }
        }
        __syncthreads();
        const int bb = row0 >> 11;          // batch
        const int t0 = row0 & 2047;         // t offset
        __half* C = (__half*)Cptr;
        #pragma unroll
        for (int i = 0; i < 16; i++) {
            const int idx = i * GTHREADS + tid;  // 0..2047
            const int n   = idx >> 4;            // 0..127 (h)
            const int ch  = idx & 15;            // 8-half chunk along t
            uint4 v = *(const uint4*)(ts + n * TSTR + ch * 8);
            *(uint4*)(C + ((size_t)bb * H_ + col0 + n) * T_ + t0 + ch * 8) = v;
        }
    }
}

// ---------------------------------------------------------------------------
// 0) Prep: x fp32->fp16 (idx < XBLKS) + W transpose [C,H]->[H,C] fp16
// ---------------------------------------------------------------------------
__global__ void __launch_bounds__(256)
prep_kernel(const float* __restrict__ x,
            const float* __restrict__ Wq, const float* __restrict__ Wk,
            const float* __restrict__ Wv)
{
    const int idx = blockIdx.x;
    if (idx < XBLKS) {
        const size_t i = ((size_t)idx * 256 + threadIdx.x) * 8;
        float4 a = *(const float4*)(x + i);
        float4 b = *(const float4*)(x + i + 4);
        __half2 h[4] = { __floats2half2_rn(a.x, a.y), __floats2half2_rn(a.z, a.w),
                         __floats2half2_rn(b.x, b.y), __floats2half2_rn(b.z, b.w) };
        *(uint4*)(g_xh + i) = *(uint4*)h;
    } else {
        const int t = idx - XBLKS;
        const int z = t >> 11;          // 0..2 (2048 tiles per matrix)
        const int rem = t & 2047;
        const int h0 = (rem & 63) * 32; // 64 h-tiles
        const int c0 = (rem >> 6) * 32; // 32 c-tiles
        const float* W = (z == 0) ? Wq : (z == 1) ? Wk : Wv;
        __half* O = g_wth + (size_t)z * H_ * C_;
        __shared__ float tile[32][33];
        const int tx = threadIdx.x & 31, ty = threadIdx.x >> 5;
        #pragma unroll
        for (int i = ty; i < 32; i += 8)
            tile[i][tx] = W[(size_t)(c0 + i) * H_ + h0 + tx];
        __syncthreads();
        #pragma unroll
        for (int i = ty; i < 32; i += 8)
            O[(size_t)(h0 + i) * C_ + c0 + tx] = __float2half_rn(tile[tx][i]);
    }
}

// ---------------------------------------------------------------------------
// 1) Q and K projections only (z=0 Q, z=1 K)
// ---------------------------------------------------------------------------
__global__ void __launch_bounds__(GTHREADS, 2)
qkproj_kernel(const float* __restrict__ bq, const float* __restrict__ bk)
{
    const int z = blockIdx.z;
    const __half* Wt = g_wth + (size_t)z * H_ * C_;
    const int row0 = blockIdx.y * 128;
    const int col0 = blockIdx.x * 128;
    if (z == 0)
        gemm_h<1>(g_xh, C_, Wt, C_, g_qh, H_, row0, col0, C_/BKH, bq, 1.0f, nullptr);
    else
        gemm_h<1>(g_xh, C_, Wt, C_, g_kh, H_, row0, col0, C_/BKH, bk, 1.0f, nullptr);
}

// ---------------------------------------------------------------------------
// 2) Merged: fused QK^T+exp (idx < 544, compact lower triangle x 4 batches)
//            + V projection->V^T (1024 tiles). Independent works, one launch.
// ---------------------------------------------------------------------------
__global__ void __launch_bounds__(GTHREADS, 2)
qk_v_kernel(const float* __restrict__ bv)
{
    const int idx = blockIdx.x;
    if (idx < 544) {
        const int b = idx / 136;
        const int t = idx % 136;
        int bi = (int)((sqrtf(8.0f * (float)t + 1.0f) - 1.0f) * 0.5f);
        while ((bi + 1) * (bi + 2) / 2 <= t) bi++;
        while (bi * (bi + 1) / 2 > t) bi--;
        const int bj = t - bi * (bi + 1) / 2;
        gemm_h<0>(g_qh + (size_t)b * T_ * H_, H_,
                  g_kh + (size_t)b * T_ * H_, H_,
                  g_p  + (size_t)b * T_ * T_, T_,
                  bi * 128, bj * 128, H_/BKH, nullptr, SCALE_LOG2E,
                  g_part + (size_t)b * T_ * 32);
    } else {
        const int v = idx - 544;
        const int col0 = (v & 15) * 128;   // 16 h-tiles
        const int row0 = (v >> 4) * 128;   // 64 t-tiles (across batches)
        gemm_h<2>(g_xh, C_, g_wth + (size_t)2 * H_ * C_, C_, g_vth, 0,
                  row0, col0, C_/BKH, bv, 1.0f, nullptr);
    }
}

// ---------------------------------------------------------------------------
// 3) O = P.V per batch (NT with V^T); 1/rowsum reduced in-CTA from g_part.
//    LARGEST-FIRST row ordering: heavy (high-row) CTAs launch first so the
//    tail waves are packed with short CTAs (LPT scheduling).
// ---------------------------------------------------------------------------
__global__ void __launch_bounds__(GTHREADS, 2)
pv_kernel(float* __restrict__ out)
{
    const int b = blockIdx.z;
    const int row0 = (int)(gridDim.y - 1 - blockIdx.y) * 128;
    const int col0 = blockIdx.x * 128;
    gemm_h<3>(g_p   + (size_t)b * T_ * T_, T_,
              g_vth + (size_t)b * H_ * T_, T_,
              out   + (size_t)b * T_ * H_, H_,
              row0, col0, (row0 + 128) / BKH, nullptr, 1.0f,
              g_part + (size_t)b * T_ * 32);
}

// ---------------------------------------------------------------------------
extern "C" void kernel_launch(void* const* d_in, const int* in_sizes, int n_in,
                              void* d_out, int out_size)
{
    const float* x  = (const float*)d_in[0];
    const float* Wq = (const float*)d_in[1];
    const float* bq = (const float*)d_in[2];
    const float* Wk = (const float*)d_in[3];
    const float* bk = (const float*)d_in[4];
    const float* Wv = (const float*)d_in[5];
    const float* bv = (const float*)d_in[6];
    float* out = (float*)d_out;

    cudaFuncSetAttribute(qkproj_kernel, cudaFuncAttributeMaxDynamicSharedMemorySize, SMEM_BYTES);
    cudaFuncSetAttribute(qk_v_kernel,   cudaFuncAttributeMaxDynamicSharedMemorySize, SMEM_BYTES);
    cudaFuncSetAttribute(pv_kernel,     cudaFuncAttributeMaxDynamicSharedMemorySize, SMEM_BYTES);

    prep_kernel  <<<dim3(XBLKS + WBLKS), dim3(256)>>>(x, Wq, Wk, Wv);
    qkproj_kernel<<<dim3(H_/128, M_/128, 2), dim3(GTHREADS), SMEM_BYTES>>>(bq, bk);
    qk_v_kernel  <<<dim3(544 + 1024), dim3(GTHREADS), SMEM_BYTES>>>(bv);
    pv_kernel    <<<dim3(H_/128, T_/128, B_), dim3(GTHREADS), SMEM_BYTES>>>(out);
}

// round 17
// speedup vs baseline: 1.4803x; 1.4803x over previous
#include <cuda_runtime.h>
#include <cuda_fp16.h>
#include <cstdint>
#include <cmath>

// Problem constants
#define B_  4
#define T_  2048
#define C_  1024
#define H_  2048
#define M_  (B_*T_)
#define SCALE_ 0.03125f             // 1024^-0.5

// Tiling: CTA 128x128, K-stage 32 halves, 4-stage cp.async pipeline
// 4 warps as 2(M) x 2(N); warp tile 64x64
#define BKH 32
#define GTHREADS 128                   // GEMM kernels
#define PITCH 80                       // bytes per 32-half row (16B-aligned, conflict-free)
#define STG   20480                    // bytes per stage: A 128*80 + B 128*80
#define SOFF_B 10240
#define NSTAGE 4
#define SINV_OFF 81920                 // per-row 1/sum cache (pv)
#define SMEM_BYTES 82432               // 4 stages + sinv[128]
#define TSTR 136                       // V^T transpose pitch (halves)

// prep grid split
#define XBLKS 4096                     // x convert: 4096 blocks * 2048 elems = M_*C_
#define WBLKS (3*2048)                 // W transpose: 3 matrices * (32x64) 32x32-tiles

// Scratch (static device globals)
__device__ __align__(256) __half g_xh  [(size_t)M_ * C_];
__device__ __align__(256) __half g_wth [(size_t)3  * H_ * C_];  // W^T [z][H][C]
__device__ __align__(256) __half g_qh  [(size_t)M_ * H_];
__device__ __align__(256) __half g_kh  [(size_t)M_ * H_];
__device__ __align__(256) __half g_vth [(size_t)B_ * H_ * T_];  // V^T [b][H][T]
__device__ __align__(256) __half g_p   [(size_t)B_ * T_ * T_];  // unnormalized exp fp16
__device__ __align__(256) float  g_part[(size_t)M_ * 32];       // per-(row,tile,half) sums

// ---------------------------------------------------------------------------
__device__ __forceinline__ uint32_t smem_u32(const void* p) {
    uint32_t a;
    asm("{ .reg .u64 t; cvta.to.shared.u64 t, %1; cvt.u32.u64 %0, t; }"
        : "=r"(a) : "l"(p));
    return a;
}
__device__ __forceinline__ void cpasync16(uint32_t dst, const void* src) {
    asm volatile("cp.async.cg.shared.global [%0], [%1], 16;"
                 :: "r"(dst), "l"(src) : "memory");
}
__device__ __forceinline__ void ldm4(uint32_t* r, uint32_t a) {
    asm volatile("ldmatrix.sync.aligned.m8n8.x4.shared.b16 {%0,%1,%2,%3}, [%4];"
        : "=r"(r[0]), "=r"(r[1]), "=r"(r[2]), "=r"(r[3]) : "r"(a));
}
__device__ __forceinline__ void mma16816(float* c, const uint32_t* a, const uint32_t* b) {
    asm volatile(
        "mma.sync.aligned.m16n8k16.row.col.f32.f16.f16.f32 "
        "{%0,%1,%2,%3}, {%4,%5,%6,%7}, {%8,%9}, {%0,%1,%2,%3};"
        : "+f"(c[0]), "+f"(c[1]), "+f"(c[2]), "+f"(c[3])
        : "r"(a[0]), "r"(a[1]), "r"(a[2]), "r"(a[3]), "r"(b[0]), "r"(b[1]));
}

// ---------------------------------------------------------------------------
// NT fp16 GEMM: acc = A[row0:+128, k] . B[col0:+128, k]^T over ktiles*32 k's.
// 4 warps, warp tile 64x64, 4-stage cp.async pipeline, fragment prefetch.
// OUT=0: qk-exp epilogue -> fp16 exp(acc*scale) to Cptr, row partials to rscale[]
// OUT=1: fp16 out + bias (q/k projection)
// OUT=2: fp16 out + bias, transposed through smem (V^T)
// OUT=3: fp32 out * per-row 1/sum (pv); rscale = g_part slice, reduced in prologue
// Requires ktiles >= 3.
// ---------------------------------------------------------------------------
template<int OUT>
__device__ void gemm_h(const __half* __restrict__ A, int lda,
                       const __half* __restrict__ Bm, int ldb,
                       void* __restrict__ Cptr, int ldc,
                       int row0, int col0, int ktiles,
                       const float* __restrict__ bias, float scale,
                       float* __restrict__ rscale)
{
    extern __shared__ char dsm[];
    const uint32_t sb = smem_u32(dsm);
    const int tid  = threadIdx.x;
    const int lane = tid & 31;
    const int warp = tid >> 5;
    const int wm   = warp & 1;        // M half (64 rows)
    const int wn   = warp >> 1;       // N half (64 cols)
    const int g    = lane >> 2;
    const int c    = lane & 3;

    // pv prologue: reduce 32 partial sums per row -> sinv (visible after first sync)
    float* sinv = (float*)(dsm + SINV_OFF);
    if (OUT == 3) {
        const float4* pp = (const float4*)(rscale + (size_t)(row0 + tid) * 32);
        float4 v0 = pp[0], v1 = pp[1], v2 = pp[2], v3 = pp[3];
        float4 v4 = pp[4], v5 = pp[5], v6 = pp[6], v7 = pp[7];
        float s = v0.x+v0.y+v0.z+v0.w + v1.x+v1.y+v1.z+v1.w
                + v2.x+v2.y+v2.z+v2.w + v3.x+v3.y+v3.z+v3.w
                + v4.x+v4.y+v4.z+v4.w + v5.x+v5.y+v5.z+v5.w
                + v6.x+v6.y+v6.z+v6.w + v7.x+v7.y+v7.z+v7.w;
        sinv[tid] = 1.0f / s;
    }

    float acc[4][8][4];
    #pragma unroll
    for (int i = 0; i < 4; i++)
        #pragma unroll
        for (int j = 0; j < 8; j++)
            #pragma unroll
            for (int l = 0; l < 4; l++) acc[i][j][l] = 0.0f;

    auto stage = [&](int kt) {
        const uint32_t ss = sb + (kt & (NSTAGE - 1)) * STG;
        const int k0 = kt * BKH;
        #pragma unroll
        for (int i = 0; i < 4; i++) {            // A: 128 rows x 4 chunks
            const int idx = i * GTHREADS + tid;
            const int r = idx >> 2, ch = idx & 3;
            cpasync16(ss + r * PITCH + ch * 16,
                      A + (size_t)(row0 + r) * lda + k0 + ch * 8);
        }
        #pragma unroll
        for (int i = 0; i < 4; i++) {            // B: 128 rows x 4 chunks
            const int idx = i * GTHREADS + tid;
            const int r = idx >> 2, ch = idx & 3;
            cpasync16(ss + SOFF_B + r * PITCH + ch * 16,
                      Bm + (size_t)(col0 + r) * ldb + k0 + ch * 8);
        }
        asm volatile("cp.async.commit_group;" ::: "memory");
    };

    // ldmatrix per-lane address components (within a stage)
    const uint32_t a_off = (uint32_t)((wm * 64 + (lane & 15)) * PITCH + ((lane >> 4) << 4));
    const uint32_t b_off = (uint32_t)(SOFF_B
                         + (wn * 64 + (lane & 7) + ((lane >> 4) << 3)) * PITCH
                         + (((lane >> 3) & 1) << 4));

    auto compute = [&](int kt) {
        const uint32_t ss = sb + (kt & (NSTAGE - 1)) * STG;
        const uint32_t sa = ss + a_off;
        const uint32_t sbb = ss + b_off;
        uint32_t af[2][4][4], bf[2][4][4];
        #pragma unroll
        for (int kk = 0; kk < 2; kk++) {
            #pragma unroll
            for (int mi = 0; mi < 4; mi++)
                ldm4(af[kk][mi], sa + mi * (16 * PITCH) + kk * 32);
            #pragma unroll
            for (int np = 0; np < 4; np++)
                ldm4(bf[kk][np], sbb + np * (16 * PITCH) + kk * 32);
        }
        #pragma unroll
        for (int kk = 0; kk < 2; kk++)
            #pragma unroll
            for (int mi = 0; mi < 4; mi++)
                #pragma unroll
                for (int ni = 0; ni < 8; ni++)
                    mma16816(acc[mi][ni], af[kk][mi],
                             &bf[kk][ni >> 1][(ni & 1) * 2]);
    };

    // 4-stage cp.async pipeline, ONE syncthreads per iteration
    stage(0);
    stage(1);
    stage(2);
    for (int kt = 0; kt < ktiles; kt++) {
        const int rem = ktiles - 1 - kt;
        if (rem >= 2)      asm volatile("cp.async.wait_group 2;" ::: "memory");
        else if (rem == 1) asm volatile("cp.async.wait_group 1;" ::: "memory");
        else               asm volatile("cp.async.wait_group 0;" ::: "memory");
        __syncthreads();
        if (kt + 3 < ktiles) stage(kt + 3);
        compute(kt);
    }
    __syncthreads();   // before epilogue smem reuse (OUT==2)

    // ------------------------------- epilogue -------------------------------
    if (OUT == 0) {
        // exp(acc*scale) -> fp16 P; per-row partial sums -> rscale slots
        __half* P = (__half*)Cptr;
        const int bj = col0 >> 7;
        const bool diag = (row0 == col0);
        #pragma unroll
        for (int mi = 0; mi < 4; mi++) {
            const int r = row0 + wm * 64 + mi * 16 + g;
            float s0 = 0.0f, s1 = 0.0f;
            #pragma unroll
            for (int ni = 0; ni < 8; ni++) {
                const int col = col0 + wn * 64 + ni * 8 + 2 * c;
                float e0 = __expf(acc[mi][ni][0] * scale);
                float e1 = __expf(acc[mi][ni][1] * scale);
                float e2 = __expf(acc[mi][ni][2] * scale);
                float e3 = __expf(acc[mi][ni][3] * scale);
                if (diag) {
                    if (col     > r    ) e0 = 0.0f;
                    if (col + 1 > r    ) e1 = 0.0f;
                    if (col     > r + 8) e2 = 0.0f;
                    if (col + 1 > r + 8) e3 = 0.0f;
                }
                s0 += e0 + e1;
                s1 += e2 + e3;
                *(__half2*)(P + (size_t)r       * ldc + col) = __floats2half2_rn(e0, e1);
                *(__half2*)(P + (size_t)(r + 8) * ldc + col) = __floats2half2_rn(e2, e3);
            }
            s0 += __shfl_xor_sync(0xffffffffu, s0, 1);
            s0 += __shfl_xor_sync(0xffffffffu, s0, 2);
            s1 += __shfl_xor_sync(0xffffffffu, s1, 1);
            s1 += __shfl_xor_sync(0xffffffffu, s1, 2);
            if (c == 0) {
                rscale[(size_t)r       * 32 + bj * 2 + wn] = s0;
                rscale[(size_t)(r + 8) * 32 + bj * 2 + wn] = s1;
            }
        }
    } else if (OUT == 3) {
        float* C = (float*)Cptr;
        #pragma unroll
        for (int mi = 0; mi < 4; mi++) {
            const int ml = wm * 64 + mi * 16 + g;
            const int m  = row0 + ml;
            const float s0 = sinv[ml], s1 = sinv[ml + 8];
            #pragma unroll
            for (int ni = 0; ni < 8; ni++) {
                const int col = col0 + wn * 64 + ni * 8 + 2 * c;
                float2 o0 = make_float2(acc[mi][ni][0] * s0, acc[mi][ni][1] * s0);
                float2 o1 = make_float2(acc[mi][ni][2] * s1, acc[mi][ni][3] * s1);
                *(float2*)(C + (size_t)m       * ldc + col) = o0;
                *(float2*)(C + (size_t)(m + 8) * ldc + col) = o1;
            }
        }
    } else if (OUT == 1) {
        __half* C = (__half*)Cptr;
        #pragma unroll
        for (int mi = 0; mi < 4; mi++) {
            const int m = row0 + wm * 64 + mi * 16 + g;
            #pragma unroll
            for (int ni = 0; ni < 8; ni++) {
                const int col = col0 + wn * 64 + ni * 8 + 2 * c;
                const float b0 = bias[col], b1 = bias[col + 1];
                __half2 h0 = __floats2half2_rn(acc[mi][ni][0] + b0, acc[mi][ni][1] + b1);
                __half2 h1 = __floats2half2_rn(acc[mi][ni][2] + b0, acc[mi][ni][3] + b1);
                *(__half2*)(C + (size_t)m       * ldc + col) = h0;
                *(__half2*)(C + (size_t)(m + 8) * ldc + col) = h1;
            }
        }
    } else {
        // V^T: transpose 128(t) x 128(h) tile through smem, coalesced 16B stores
        __half* ts = (__half*)dsm;
        #pragma unroll
        for (int mi = 0; mi < 4; mi++) {
            const int ml = wm * 64 + mi * 16 + g;
            #pragma unroll
            for (int ni = 0; ni < 8; ni++) {
                const int nl = wn * 64 + ni * 8 + 2 * c;
                const float b0 = bias[col0 + nl], b1 = bias[col0 + nl + 1];
                ts[(nl    ) * TSTR + ml    ] = __float2half_rn(acc[mi][ni][0] + b0);
                ts[(nl + 1) * TSTR + ml    ] = __float2half_rn(acc[mi][ni][1] + b1);
                ts[(nl    ) * TSTR + ml + 8] = __float2half_rn(acc[mi][ni][2] + b0);
                ts[(nl + 1) * TSTR + ml + 8] = __float2half_rn(acc[mi][ni][3] + b1);
            }
        }
        __syncthreads();
        const int bb = row0 >> 11;          // batch
        const int t0 = row0 & 2047;         // t offset
        __half* C = (__half*)Cptr;
        #pragma unroll
        for (int i = 0; i < 16; i++) {
            const int idx = i * GTHREADS + tid;  // 0..2047
            const int n   = idx >> 4;            // 0..127 (h)
            const int ch  = idx & 15;            // 8-half chunk along t
            uint4 v = *(const uint4*)(ts + n * TSTR + ch * 8);
            *(uint4*)(C + ((size_t)bb * H_ + col0 + n) * T_ + t0 + ch * 8) = v;
        }
    }
}

// ---------------------------------------------------------------------------
// 0) Prep: x fp32->fp16 (idx < XBLKS) + W transpose [C,H]->[H,C] fp16
// ---------------------------------------------------------------------------
__global__ void __launch_bounds__(256)
prep_kernel(const float* __restrict__ x,
            const float* __restrict__ Wq, const float* __restrict__ Wk,
            const float* __restrict__ Wv)
{
    const int idx = blockIdx.x;
    if (idx < XBLKS) {
        const size_t i = ((size_t)idx * 256 + threadIdx.x) * 8;
        float4 a = *(const float4*)(x + i);
        float4 b = *(const float4*)(x + i + 4);
        __half2 h[4] = { __floats2half2_rn(a.x, a.y), __floats2half2_rn(a.z, a.w),
                         __floats2half2_rn(b.x, b.y), __floats2half2_rn(b.z, b.w) };
        *(uint4*)(g_xh + i) = *(uint4*)h;
    } else {
        const int t = idx - XBLKS;
        const int z = t >> 11;          // 0..2 (2048 tiles per matrix)
        const int rem = t & 2047;
        const int h0 = (rem & 63) * 32; // 64 h-tiles
        const int c0 = (rem >> 6) * 32; // 32 c-tiles
        const float* W = (z == 0) ? Wq : (z == 1) ? Wk : Wv;
        __half* O = g_wth + (size_t)z * H_ * C_;
        __shared__ float tile[32][33];
        const int tx = threadIdx.x & 31, ty = threadIdx.x >> 5;
        #pragma unroll
        for (int i = ty; i < 32; i += 8)
            tile[i][tx] = W[(size_t)(c0 + i) * H_ + h0 + tx];
        __syncthreads();
        #pragma unroll
        for (int i = ty; i < 32; i += 8)
            O[(size_t)(h0 + i) * C_ + c0 + tx] = __float2half_rn(tile[tx][i]);
    }
}

// ---------------------------------------------------------------------------
// 1) Q and K projections only (z=0 Q, z=1 K)
// ---------------------------------------------------------------------------
__global__ void __launch_bounds__(GTHREADS, 2)
qkproj_kernel(const float* __restrict__ bq, const float* __restrict__ bk)
{
    const int z = blockIdx.z;
    const __half* Wt = g_wth + (size_t)z * H_ * C_;
    const int row0 = blockIdx.y * 128;
    const int col0 = blockIdx.x * 128;
    if (z == 0)
        gemm_h<1>(g_xh, C_, Wt, C_, g_qh, H_, row0, col0, C_/BKH, bq, 1.0f, nullptr);
    else
        gemm_h<1>(g_xh, C_, Wt, C_, g_kh, H_, row0, col0, C_/BKH, bk, 1.0f, nullptr);
}

// ---------------------------------------------------------------------------
// 2) Merged: fused QK^T+exp (idx < 544, compact lower triangle x 4 batches)
//            + V projection->V^T (1024 tiles). Independent works, one launch.
// ---------------------------------------------------------------------------
__global__ void __launch_bounds__(GTHREADS, 2)
qk_v_kernel(const float* __restrict__ bv)
{
    const int idx = blockIdx.x;
    if (idx < 544) {
        const int b = idx / 136;
        const int t = idx % 136;
        int bi = (int)((sqrtf(8.0f * (float)t + 1.0f) - 1.0f) * 0.5f);
        while ((bi + 1) * (bi + 2) / 2 <= t) bi++;
        while (bi * (bi + 1) / 2 > t) bi--;
        const int bj = t - bi * (bi + 1) / 2;
        gemm_h<0>(g_qh + (size_t)b * T_ * H_, H_,
                  g_kh + (size_t)b * T_ * H_, H_,
                  g_p  + (size_t)b * T_ * T_, T_,
                  bi * 128, bj * 128, H_/BKH, nullptr, SCALE_,
                  g_part + (size_t)b * T_ * 32);
    } else {
        const int v = idx - 544;
        const int col0 = (v & 15) * 128;   // 16 h-tiles
        const int row0 = (v >> 4) * 128;   // 64 t-tiles (across batches)
        gemm_h<2>(g_xh, C_, g_wth + (size_t)2 * H_ * C_, C_, g_vth, 0,
                  row0, col0, C_/BKH, bv, 1.0f, nullptr);
    }
}

// ---------------------------------------------------------------------------
// 3) O = P.V per batch (NT with V^T); 1/rowsum reduced in-CTA from g_part.
//    BALANCED WAVES: blockIdx.x (fastest) walks the 16 variable-work ROW
//    tiles, so every 16 consecutive CTAs carry one of each weight and share
//    the same V^T B-tile (L2 reuse). blockIdx.y walks the uniform col tiles.
// ---------------------------------------------------------------------------
__global__ void __launch_bounds__(GTHREADS, 2)
pv_kernel(float* __restrict__ out)
{
    const int b = blockIdx.z;
    const int row0 = blockIdx.x * 128;   // variable-work axis, fastest
    const int col0 = blockIdx.y * 128;   // uniform axis
    gemm_h<3>(g_p   + (size_t)b * T_ * T_, T_,
              g_vth + (size_t)b * H_ * T_, T_,
              out   + (size_t)b * T_ * H_, H_,
              row0, col0, (row0 + 128) / BKH, nullptr, 1.0f,
              g_part + (size_t)b * T_ * 32);
}

// ---------------------------------------------------------------------------
extern "C" void kernel_launch(void* const* d_in, const int* in_sizes, int n_in,
                              void* d_out, int out_size)
{
    const float* x  = (const float*)d_in[0];
    const float* Wq = (const float*)d_in[1];
    const float* bq = (const float*)d_in[2];
    const float* Wk = (const float*)d_in[3];
    const float* bk = (const float*)d_in[4];
    const float* Wv = (const float*)d_in[5];
    const float* bv = (const float*)d_in[6];
    float* out = (float*)d_out;

    cudaFuncSetAttribute(qkproj_kernel, cudaFuncAttributeMaxDynamicSharedMemorySize, SMEM_BYTES);
    cudaFuncSetAttribute(qk_v_kernel,   cudaFuncAttributeMaxDynamicSharedMemorySize, SMEM_BYTES);
    cudaFuncSetAttribute(pv_kernel,     cudaFuncAttributeMaxDynamicSharedMemorySize, SMEM_BYTES);

    prep_kernel  <<<dim3(XBLKS + WBLKS), dim3(256)>>>(x, Wq, Wk, Wv);
    qkproj_kernel<<<dim3(H_/128, M_/128, 2), dim3(GTHREADS), SMEM_BYTES>>>(bq, bk);
    qk_v_kernel  <<<dim3(544 + 1024), dim3(GTHREADS), SMEM_BYTES>>>(bv);
    pv_kernel    <<<dim3(T_/128, H_/128, B_), dim3(GTHREADS), SMEM_BYTES>>>(out);
}